// round 1
// baseline (speedup 1.0000x reference)
#include <cuda_runtime.h>
#include <cuda_bf16.h>

// Embedder: per position p (of B*S=524288), output 64 floats:
//   type_mask[p]==1 -> emb_table[(int)input_ids[p]]          (gather, 256B row)
//   type_mask[p]==0 -> w2 @ relu(w1*x + b1) + b2             (1->16->64 MLP)
//
// Layout: 16 threads per position, each owning one float4 (4 of the 64 dims).
// Global thread id maps linearly to output float4 index -> perfectly coalesced
// 128-bit stores. Token path does one coalesced float4 gather from the
// embedding row (table fits in L2). Numeric path computes h[16] then 4 dots.

#define EMBED_DIM 64
#define HIDDEN 16

__global__ __launch_bounds__(256) void embedder_kernel(
    const float* __restrict__ input_ids,
    const int* __restrict__ type_mask,
    const float4* __restrict__ emb_table,   // [VOCAB][16] float4
    const float* __restrict__ w1,           // [16]
    const float* __restrict__ b1,           // [16]
    const float* __restrict__ w2,           // [64][16]
    const float* __restrict__ b2,           // [64]
    float4* __restrict__ out,               // [B*S*16] float4
    int n_vec)                              // total float4 count
{
    int tid = blockIdx.x * blockDim.x + threadIdx.x;
    if (tid >= n_vec) return;

    int pos = tid >> 4;       // position index
    int q   = tid & 15;       // which float4 of the 64-dim row

    float x = input_ids[pos];
    int   m = type_mask[pos];

    float4 r;
    if (m) {
        // token path: gather one float4 from the embedding row
        int id = (int)x;
        r = emb_table[id * 16 + q];
    } else {
        // numeric path: h = relu(w1*x + b1); r[c] = dot(w2[d], h) + b2[d]
        float h[HIDDEN];
        #pragma unroll
        for (int j = 0; j < HIDDEN; j++)
            h[j] = fmaxf(fmaf(__ldg(&w1[j]), x, __ldg(&b1[j])), 0.0f);

        float acc[4];
        int d0 = q * 4;
        #pragma unroll
        for (int c = 0; c < 4; c++) {
            int d = d0 + c;
            float s = __ldg(&b2[d]);
            #pragma unroll
            for (int j = 0; j < HIDDEN; j++)
                s = fmaf(__ldg(&w2[d * HIDDEN + j]), h[j], s);
            acc[c] = s;
        }
        r.x = acc[0]; r.y = acc[1]; r.z = acc[2]; r.w = acc[3];
    }
    out[tid] = r;
}

extern "C" void kernel_launch(void* const* d_in, const int* in_sizes, int n_in,
                              void* d_out, int out_size) {
    const float*  input_ids = (const float*)d_in[0];
    const int*    type_mask = (const int*)d_in[1];
    const float4* emb_table = (const float4*)d_in[2];
    const float*  w1        = (const float*)d_in[3];
    const float*  b1        = (const float*)d_in[4];
    const float*  w2        = (const float*)d_in[5];
    const float*  b2        = (const float*)d_in[6];
    float4* out = (float4*)d_out;

    int n_vec = out_size / 4;               // float4 count
    int threads = 256;
    int blocks = (n_vec + threads - 1) / threads;
    embedder_kernel<<<blocks, threads>>>(input_ids, type_mask, emb_table,
                                         w1, b1, w2, b2, out, n_vec);
}

// round 2
// speedup vs baseline: 6.3124x; 6.3124x over previous
#include <cuda_runtime.h>
#include <cuda_bf16.h>

// Embedder, R2: all weights register-resident, grid-stride loop.
//
// Per position p (of B*S=524288), output 64 floats:
//   type_mask[p]==1 -> emb_table[(int)input_ids[p]]   (256B coalesced gather, L2-resident table)
//   type_mask[p]==0 -> w2 @ relu(w1*x + b1) + b2      (96 reg-resident FMAs)
//
// 16 threads per position; lane role q = tid & 15 is loop-invariant (grid and
// block sizes are multiples of 16), so each thread loads its 64-float w2 slice
// + w1/b1/b2 into registers ONCE. Per-iteration memory ops: 2 broadcast loads,
// optional 1 float4 gather, 1 float4 store. This removes the L1-saturating
// per-position weight LDGs that made R1 97% L1-bound.

#define HIDDEN 16

__global__ void __launch_bounds__(256, 2) embedder_kernel(
    const float* __restrict__ input_ids,
    const int* __restrict__ type_mask,
    const float4* __restrict__ emb_table,   // [VOCAB][16] float4
    const float* __restrict__ w1,           // [16]
    const float* __restrict__ b1,           // [16]
    const float* __restrict__ w2,           // [64][16]
    const float* __restrict__ b2,           // [64]
    float4* __restrict__ out,               // [B*S*16] float4
    int n_vec)
{
    const int tid0   = blockIdx.x * blockDim.x + threadIdx.x;
    const int stride = gridDim.x * blockDim.x;   // multiple of 16
    const int q  = threadIdx.x & 15;             // float4-slot role, loop-invariant
    const int d0 = q * 4;                        // first output dim owned

    // ---- one-time register prologue (amortized over ~28+ iterations) ----
    float w1r[HIDDEN], b1r[HIDDEN];
    #pragma unroll
    for (int j = 0; j < HIDDEN; j++) { w1r[j] = w1[j]; b1r[j] = b1[j]; }

    float w2r[4][HIDDEN], b2r[4];
    #pragma unroll
    for (int c = 0; c < 4; c++) {
        b2r[c] = b2[d0 + c];
        #pragma unroll
        for (int j = 0; j < HIDDEN; j++)
            w2r[c][j] = w2[(d0 + c) * HIDDEN + j];
    }

    // ---- main loop: one float4 of output per iteration ----
    for (int v = tid0; v < n_vec; v += stride) {
        int   pos = v >> 4;
        float x   = __ldg(&input_ids[pos]);     // broadcast across the 16-lane group
        int   m   = __ldg(&type_mask[pos]);

        float4 r;
        if (m) {
            // token path: coalesced 256B row gather (2 cache lines / 16 lanes)
            r = __ldg(&emb_table[((int)x) * 16 + q]);
        } else {
            // numeric path: fully register-resident MLP
            float acc0 = b2r[0], acc1 = b2r[1], acc2 = b2r[2], acc3 = b2r[3];
            #pragma unroll
            for (int j = 0; j < HIDDEN; j++) {
                float h = fmaxf(fmaf(w1r[j], x, b1r[j]), 0.0f);
                acc0 = fmaf(w2r[0][j], h, acc0);
                acc1 = fmaf(w2r[1][j], h, acc1);
                acc2 = fmaf(w2r[2][j], h, acc2);
                acc3 = fmaf(w2r[3][j], h, acc3);
            }
            r = make_float4(acc0, acc1, acc2, acc3);
        }
        out[v] = r;   // perfectly coalesced 128-bit stores
    }
}

extern "C" void kernel_launch(void* const* d_in, const int* in_sizes, int n_in,
                              void* d_out, int out_size) {
    const float*  input_ids = (const float*)d_in[0];
    const int*    type_mask = (const int*)d_in[1];
    const float4* emb_table = (const float4*)d_in[2];
    const float*  w1        = (const float*)d_in[3];
    const float*  b1        = (const float*)d_in[4];
    const float*  w2        = (const float*)d_in[5];
    const float*  b2        = (const float*)d_in[6];
    float4* out = (float4*)d_out;

    int n_vec = out_size / 4;               // total float4 count (8.4M)

    // bounded grid: amortizes the register prologue; stride stays a multiple
    // of 16 so each thread's lane role q is loop-invariant.
    int threads = 256;
    int max_blocks = 1184;                  // ~8 CTAs' worth of waves per SM
    int blocks = (n_vec + threads - 1) / threads;
    if (blocks > max_blocks) blocks = max_blocks;

    embedder_kernel<<<blocks, threads>>>(input_ids, type_mask, emb_table,
                                         w1, b1, w2, b2, out, n_vec);
}

// round 3
// speedup vs baseline: 8.0081x; 1.2686x over previous
#include <cuda_runtime.h>
#include <cuda_bf16.h>

// Embedder R3: piecewise-linear collapse of the numeric MLP.
//
// out[pos] = mask ? emb_table[id]                       (256B coalesced gather)
//                 : w2 @ relu(w1*x + b1) + b2
//
// For x >= xlo (largest ReLU breakpoint, ~0.4 here), the ReLU active-set is
// constant, so the MLP is EXACTLY  A*x + C  with A,C precomputed per thread
// (4 floats each for this thread's float4 slice). x < xlo+0.5 falls back to
// the full MLP from global memory (a handful of positions — always correct,
// never fast-path-dependent on data for correctness).
//
// 16 threads per position, one float4 each -> fully coalesced 128-bit stores.
// Gather made unconditional with safe index (row 0 stays L1-hot for numeric
// lanes) -> branch-free hot body: 2 scalar loads + 1 float4 gather + 4 FMAs
// + select + 1 float4 store. ~35 regs -> high occupancy to hide L2 latency.

#define HIDDEN 16

__global__ void __launch_bounds__(256) embedder_kernel(
    const float* __restrict__ input_ids,
    const int* __restrict__ type_mask,
    const float4* __restrict__ emb_table,   // [VOCAB][16] float4
    const float* __restrict__ w1,           // [16]
    const float* __restrict__ b1,           // [16]
    const float* __restrict__ w2,           // [64][16]
    const float* __restrict__ b2,           // [64]
    float4* __restrict__ out,               // [B*S*16] float4
    int n_vec)
{
    const int tid0   = blockIdx.x * blockDim.x + threadIdx.x;
    const int stride = gridDim.x * blockDim.x;   // multiple of 16
    const int q  = threadIdx.x & 15;
    const int d0 = q * 4;

    // ---- prologue: fold MLP into affine A*x + C for the stable active-set ----
    float A0 = 0.f, A1 = 0.f, A2 = 0.f, A3 = 0.f;
    float C0 = b2[d0+0], C1 = b2[d0+1], C2 = b2[d0+2], C3 = b2[d0+3];
    float xlo = -3.4e38f;
    #pragma unroll
    for (int j = 0; j < HIDDEN; j++) {
        float w1j = w1[j], b1j = b1[j];
        float w20 = w2[(d0+0)*HIDDEN + j];
        float w21 = w2[(d0+1)*HIDDEN + j];
        float w22 = w2[(d0+2)*HIDDEN + j];
        float w23 = w2[(d0+3)*HIDDEN + j];
        if (w1j != 0.f) {
            // both signs of w1j yield a LOWER bound on x for a fixed active-set
            xlo = fmaxf(xlo, -b1j / w1j);
            if (w1j > 0.f) {   // unit active for large x
                A0 = fmaf(w20, w1j, A0); C0 = fmaf(w20, b1j, C0);
                A1 = fmaf(w21, w1j, A1); C1 = fmaf(w21, b1j, C1);
                A2 = fmaf(w22, w1j, A2); C2 = fmaf(w22, b1j, C2);
                A3 = fmaf(w23, w1j, A3); C3 = fmaf(w23, b1j, C3);
            }
        } else {               // constant unit: relu(b1j)
            float hc = fmaxf(b1j, 0.f);
            C0 = fmaf(w20, hc, C0); C1 = fmaf(w21, hc, C1);
            C2 = fmaf(w22, hc, C2); C3 = fmaf(w23, hc, C3);
        }
    }
    const float xguard = xlo + 0.5f;   // margin swallows divide rounding

    // ---- main loop, 2x unrolled for load-level parallelism ----
    int v = tid0;
    for (; v + stride < n_vec; v += 2 * stride) {
        int v1 = v + stride;
        int p0 = v  >> 4;
        int p1 = v1 >> 4;
        float x0 = __ldg(&input_ids[p0]);
        float x1 = __ldg(&input_ids[p1]);
        int   m0 = __ldg(&type_mask[p0]);
        int   m1 = __ldg(&type_mask[p1]);

        int id0 = m0 ? (int)x0 : 0;          // row 0 is L1-hot for numeric lanes
        int id1 = m1 ? (int)x1 : 0;
        float4 g0 = __ldg(&emb_table[id0 * 16 + q]);
        float4 g1 = __ldg(&emb_table[id1 * 16 + q]);

        float4 f0 = make_float4(fmaf(A0,x0,C0), fmaf(A1,x0,C1),
                                fmaf(A2,x0,C2), fmaf(A3,x0,C3));
        float4 f1 = make_float4(fmaf(A0,x1,C0), fmaf(A1,x1,C1),
                                fmaf(A2,x1,C2), fmaf(A3,x1,C3));

        float4 r0 = m0 ? g0 : f0;
        float4 r1 = m1 ? g1 : f1;

        if (!m0 && x0 < xguard) {            // rare exact fallback
            float a[4] = {b2[d0], b2[d0+1], b2[d0+2], b2[d0+3]};
            #pragma unroll
            for (int j = 0; j < HIDDEN; j++) {
                float h = fmaxf(fmaf(w1[j], x0, b1[j]), 0.f);
                #pragma unroll
                for (int c = 0; c < 4; c++) a[c] = fmaf(w2[(d0+c)*HIDDEN+j], h, a[c]);
            }
            r0 = make_float4(a[0], a[1], a[2], a[3]);
        }
        if (!m1 && x1 < xguard) {
            float a[4] = {b2[d0], b2[d0+1], b2[d0+2], b2[d0+3]};
            #pragma unroll
            for (int j = 0; j < HIDDEN; j++) {
                float h = fmaxf(fmaf(w1[j], x1, b1[j]), 0.f);
                #pragma unroll
                for (int c = 0; c < 4; c++) a[c] = fmaf(w2[(d0+c)*HIDDEN+j], h, a[c]);
            }
            r1 = make_float4(a[0], a[1], a[2], a[3]);
        }

        out[v]  = r0;
        out[v1] = r1;
    }
    if (v < n_vec) {                          // tail
        int p = v >> 4;
        float x = __ldg(&input_ids[p]);
        int   m = __ldg(&type_mask[p]);
        int  id = m ? (int)x : 0;
        float4 g = __ldg(&emb_table[id * 16 + q]);
        float4 r = m ? g : make_float4(fmaf(A0,x,C0), fmaf(A1,x,C1),
                                       fmaf(A2,x,C2), fmaf(A3,x,C3));
        if (!m && x < xguard) {
            float a[4] = {b2[d0], b2[d0+1], b2[d0+2], b2[d0+3]};
            #pragma unroll
            for (int j = 0; j < HIDDEN; j++) {
                float h = fmaxf(fmaf(w1[j], x, b1[j]), 0.f);
                #pragma unroll
                for (int c = 0; c < 4; c++) a[c] = fmaf(w2[(d0+c)*HIDDEN+j], h, a[c]);
            }
            r = make_float4(a[0], a[1], a[2], a[3]);
        }
        out[v] = r;
    }
}

extern "C" void kernel_launch(void* const* d_in, const int* in_sizes, int n_in,
                              void* d_out, int out_size) {
    const float*  input_ids = (const float*)d_in[0];
    const int*    type_mask = (const int*)d_in[1];
    const float4* emb_table = (const float4*)d_in[2];
    const float*  w1        = (const float*)d_in[3];
    const float*  b1        = (const float*)d_in[4];
    const float*  w2        = (const float*)d_in[5];
    const float*  b2        = (const float*)d_in[6];
    float4* out = (float4*)d_out;

    int n_vec = out_size / 4;               // total float4 count (8.4M)

    int threads = 256;
    int max_blocks = 1184;                  // 8 CTAs/SM target, low-reg kernel
    int blocks = (n_vec + threads - 1) / threads;
    if (blocks > max_blocks) blocks = max_blocks;

    embedder_kernel<<<blocks, threads>>>(input_ids, type_mask, emb_table,
                                         w1, b1, w2, b2, out, n_vec);
}

// round 4
// speedup vs baseline: 8.1456x; 1.0172x over previous
#include <cuda_runtime.h>
#include <cuda_bf16.h>

// Embedder R4: three-launch split to keep the hot kernel branch-free and
// register-lean.
//   1) init_kernel:   xguard = max_j(-b1[j]/w1[j]) + 0.5   -> __device__ global
//   2) embedder_kernel: branch-free. numeric -> affine A*x+C (exact for
//      x >= xguard, wrong-but-overwritten below); token -> 256B gather.
//   3) fixup_kernel:  rare positions (mask==0 && x<xguard) get the exact MLP
//      recomputed and overwritten. Always correct; rarity only affects speed.
//
// Hot-kernel body: 2 scalar loads + 1 float4 gather + 4 FMAs + select +
// 1 float4 store, 4x unrolled grid-stride. Target <=40 regs -> 48+ warps/SM.

#define HIDDEN 16
#define NPOS (128 * 4096)

__device__ float g_xguard;

__global__ void init_kernel(const float* __restrict__ w1,
                            const float* __restrict__ b1) {
    if (threadIdx.x == 0) {
        float xlo = -3.4e38f;
        #pragma unroll
        for (int j = 0; j < HIDDEN; j++) {
            float w = w1[j];
            if (w != 0.f) xlo = fmaxf(xlo, -b1[j] / w);
        }
        g_xguard = xlo + 0.5f;   // margin swallows divide rounding
    }
}

__global__ void __launch_bounds__(256) embedder_kernel(
    const float* __restrict__ input_ids,
    const int* __restrict__ type_mask,
    const float4* __restrict__ emb_table,   // [VOCAB][16] float4
    const float* __restrict__ w1,
    const float* __restrict__ b1,
    const float* __restrict__ w2,           // [64][16]
    const float* __restrict__ b2,
    float4* __restrict__ out,
    int n_vec)
{
    const int tid0   = blockIdx.x * blockDim.x + threadIdx.x;
    const int stride = gridDim.x * blockDim.x;   // multiple of 16
    const int q  = threadIdx.x & 15;
    const int d0 = q * 4;

    // fold MLP into affine A*x + C for the large-x active-set
    float A0 = 0.f, A1 = 0.f, A2 = 0.f, A3 = 0.f;
    float C0 = b2[d0+0], C1 = b2[d0+1], C2 = b2[d0+2], C3 = b2[d0+3];
    #pragma unroll
    for (int j = 0; j < HIDDEN; j++) {
        float w1j = w1[j], b1j = b1[j];
        float w20 = w2[(d0+0)*HIDDEN + j];
        float w21 = w2[(d0+1)*HIDDEN + j];
        float w22 = w2[(d0+2)*HIDDEN + j];
        float w23 = w2[(d0+3)*HIDDEN + j];
        if (w1j > 0.f) {          // unit active for x above all breakpoints
            A0 = fmaf(w20, w1j, A0); C0 = fmaf(w20, b1j, C0);
            A1 = fmaf(w21, w1j, A1); C1 = fmaf(w21, b1j, C1);
            A2 = fmaf(w22, w1j, A2); C2 = fmaf(w22, b1j, C2);
            A3 = fmaf(w23, w1j, A3); C3 = fmaf(w23, b1j, C3);
        } else if (w1j == 0.f) {  // constant unit: relu(b1j)
            float hc = fmaxf(b1j, 0.f);
            C0 = fmaf(w20, hc, C0); C1 = fmaf(w21, hc, C1);
            C2 = fmaf(w22, hc, C2); C3 = fmaf(w23, hc, C3);
        }                         // w1j < 0: inactive for large x
    }

    int v = tid0;
    // 4x-unrolled main loop: 8 independent loads in flight per thread
    for (; v + 3 * stride < n_vec; v += 4 * stride) {
        #pragma unroll
        for (int u = 0; u < 4; u++) {
            int vu = v + u * stride;
            int p  = vu >> 4;
            float x = __ldg(&input_ids[p]);
            int   m = __ldg(&type_mask[p]);
            int  id = m ? (int)x : 0;        // row 0 stays L1-hot
            float4 g = __ldg(&emb_table[id * 16 + q]);
            float4 f = make_float4(fmaf(A0,x,C0), fmaf(A1,x,C1),
                                   fmaf(A2,x,C2), fmaf(A3,x,C3));
            out[vu] = m ? g : f;
        }
    }
    for (; v < n_vec; v += stride) {
        int p  = v >> 4;
        float x = __ldg(&input_ids[p]);
        int   m = __ldg(&type_mask[p]);
        int  id = m ? (int)x : 0;
        float4 g = __ldg(&emb_table[id * 16 + q]);
        float4 f = make_float4(fmaf(A0,x,C0), fmaf(A1,x,C1),
                               fmaf(A2,x,C2), fmaf(A3,x,C3));
        out[v] = m ? g : f;
    }
}

__global__ void __launch_bounds__(256) fixup_kernel(
    const float* __restrict__ input_ids,
    const int* __restrict__ type_mask,
    const float* __restrict__ w1,
    const float* __restrict__ b1,
    const float* __restrict__ w2,
    const float* __restrict__ b2,
    float4* __restrict__ out)
{
    int pos = blockIdx.x * blockDim.x + threadIdx.x;
    if (pos >= NPOS) return;
    if (type_mask[pos]) return;
    float x = input_ids[pos];
    if (x >= g_xguard) return;               // affine path was exact

    // rare: recompute exact MLP for all 64 dims and overwrite
    float h[HIDDEN];
    #pragma unroll
    for (int j = 0; j < HIDDEN; j++)
        h[j] = fmaxf(fmaf(w1[j], x, b1[j]), 0.f);

    #pragma unroll
    for (int qq = 0; qq < 16; qq++) {
        float a[4];
        #pragma unroll
        for (int c = 0; c < 4; c++) {
            int d = qq * 4 + c;
            float s = b2[d];
            #pragma unroll
            for (int j = 0; j < HIDDEN; j++)
                s = fmaf(w2[d * HIDDEN + j], h[j], s);
            a[c] = s;
        }
        out[pos * 16 + qq] = make_float4(a[0], a[1], a[2], a[3]);
    }
}

extern "C" void kernel_launch(void* const* d_in, const int* in_sizes, int n_in,
                              void* d_out, int out_size) {
    const float*  input_ids = (const float*)d_in[0];
    const int*    type_mask = (const int*)d_in[1];
    const float4* emb_table = (const float4*)d_in[2];
    const float*  w1        = (const float*)d_in[3];
    const float*  b1        = (const float*)d_in[4];
    const float*  w2        = (const float*)d_in[5];
    const float*  b2        = (const float*)d_in[6];
    float4* out = (float4*)d_out;

    int n_vec = out_size / 4;

    init_kernel<<<1, 32>>>(w1, b1);

    int threads = 256;
    int max_blocks = 1184;
    int blocks = (n_vec + threads - 1) / threads;
    if (blocks > max_blocks) blocks = max_blocks;
    embedder_kernel<<<blocks, threads>>>(input_ids, type_mask, emb_table,
                                         w1, b1, w2, b2, out, n_vec);

    fixup_kernel<<<(NPOS + 255) / 256, 256>>>(input_ids, type_mask,
                                              w1, b1, w2, b2, out);
}

// round 5
// speedup vs baseline: 11.6883x; 1.4349x over previous
#include <cuda_runtime.h>
#include <cuda_bf16.h>

// Embedder R5: precomputed affine tables, one-shot lean hot kernel.
//   1) prep_kernel (16 thr): fold MLP -> g_A[16],g_C[16] (float4) + g_xguard.
//   2) embedder_kernel: full grid, ONE float4 per thread, ~25 regs -> 64
//      warps/SM. numeric -> A*x+C (2 L1-hot 16B loads); token -> predicated
//      256B gather. Coalesced 128-bit stores.
//   3) fixup_kernel: rare (mask==0 && x<g_xguard) positions get the exact MLP
//      recomputed. Always correct; rarity only affects speed.

#define HIDDEN 16
#define NPOS (128 * 4096)

__device__ float4 g_A[16];
__device__ float4 g_C[16];
__device__ float  g_xguard;

__global__ void prep_kernel(const float* __restrict__ w1,
                            const float* __restrict__ b1,
                            const float* __restrict__ w2,
                            const float* __restrict__ b2) {
    int q = threadIdx.x;            // 0..15, owns dims 4q..4q+3
    if (q >= 16) return;
    int d0 = q * 4;

    float A[4] = {0.f, 0.f, 0.f, 0.f};
    float C[4] = {b2[d0], b2[d0+1], b2[d0+2], b2[d0+3]};
    float xlo = -3.4e38f;
    #pragma unroll
    for (int j = 0; j < HIDDEN; j++) {
        float w1j = w1[j], b1j = b1[j];
        if (w1j != 0.f) xlo = fmaxf(xlo, -b1j / w1j);
        #pragma unroll
        for (int c = 0; c < 4; c++) {
            float w2v = w2[(d0 + c) * HIDDEN + j];
            if (w1j > 0.f) {            // active for large x
                A[c] = fmaf(w2v, w1j, A[c]);
                C[c] = fmaf(w2v, b1j, C[c]);
            } else if (w1j == 0.f) {    // constant unit
                C[c] = fmaf(w2v, fmaxf(b1j, 0.f), C[c]);
            }
        }
    }
    g_A[q] = make_float4(A[0], A[1], A[2], A[3]);
    g_C[q] = make_float4(C[0], C[1], C[2], C[3]);
    if (q == 0) g_xguard = xlo + 0.5f;   // margin swallows divide rounding
}

__global__ void __launch_bounds__(256) embedder_kernel(
    const float* __restrict__ input_ids,
    const int* __restrict__ type_mask,
    const float4* __restrict__ emb_table,   // [VOCAB][16] float4
    float4* __restrict__ out,
    int n_vec)
{
    int v = blockIdx.x * blockDim.x + threadIdx.x;
    if (v >= n_vec) return;
    int q   = v & 15;
    int pos = v >> 4;

    float x = __ldg(&input_ids[pos]);
    int   m = __ldg(&type_mask[pos]);

    float4 r;
    if (m) {
        r = __ldg(&emb_table[((int)x) * 16 + q]);   // coalesced 256B row
    } else {
        float4 A = g_A[q];                          // L1-hot 16B
        float4 C = g_C[q];
        r = make_float4(fmaf(A.x, x, C.x), fmaf(A.y, x, C.y),
                        fmaf(A.z, x, C.z), fmaf(A.w, x, C.w));
    }
    out[v] = r;
}

__global__ void __launch_bounds__(256) fixup_kernel(
    const float* __restrict__ input_ids,
    const int* __restrict__ type_mask,
    const float* __restrict__ w1,
    const float* __restrict__ b1,
    const float* __restrict__ w2,
    const float* __restrict__ b2,
    float4* __restrict__ out)
{
    int pos = blockIdx.x * blockDim.x + threadIdx.x;
    if (pos >= NPOS) return;
    if (type_mask[pos]) return;
    float x = input_ids[pos];
    if (x >= g_xguard) return;               // affine path was exact

    float h[HIDDEN];
    #pragma unroll
    for (int j = 0; j < HIDDEN; j++)
        h[j] = fmaxf(fmaf(w1[j], x, b1[j]), 0.f);

    #pragma unroll
    for (int qq = 0; qq < 16; qq++) {
        float a[4];
        #pragma unroll
        for (int c = 0; c < 4; c++) {
            int d = qq * 4 + c;
            float s = b2[d];
            #pragma unroll
            for (int j = 0; j < HIDDEN; j++)
                s = fmaf(w2[d * HIDDEN + j], h[j], s);
            a[c] = s;
        }
        out[pos * 16 + qq] = make_float4(a[0], a[1], a[2], a[3]);
    }
}

extern "C" void kernel_launch(void* const* d_in, const int* in_sizes, int n_in,
                              void* d_out, int out_size) {
    const float*  input_ids = (const float*)d_in[0];
    const int*    type_mask = (const int*)d_in[1];
    const float4* emb_table = (const float4*)d_in[2];
    const float*  w1        = (const float*)d_in[3];
    const float*  b1        = (const float*)d_in[4];
    const float*  w2        = (const float*)d_in[5];
    const float*  b2        = (const float*)d_in[6];
    float4* out = (float4*)d_out;

    int n_vec = out_size / 4;               // 8.4M float4s

    prep_kernel<<<1, 16>>>(w1, b1, w2, b2);

    int threads = 256;
    int blocks = (n_vec + threads - 1) / threads;   // full grid, one-shot
    embedder_kernel<<<blocks, threads>>>(input_ids, type_mask, emb_table,
                                         out, n_vec);

    fixup_kernel<<<(NPOS + 255) / 256, 256>>>(input_ids, type_mask,
                                              w1, b1, w2, b2, out);
}

// round 6
// speedup vs baseline: 15.3244x; 1.3111x over previous
#include <cuda_runtime.h>
#include <cuda_bf16.h>

// Embedder R6: cache-policy control + list-based fixup.
//   prep:  fold MLP -> g_A/g_C + g_xguard; reset rare-position counter.
//   main:  one float4/thread. token -> __ldcg gather (L2-only; table stays
//          L2-resident because output stores use __stcs evict-first).
//          numeric -> affine A*x+C. Rare (x<xguard) numeric positions are
//          appended to g_fix_list (lane q==0 of the 16-lane group).
//   fixup: persistent small kernel over the recorded list only — exact MLP
//          overwrite. Always correct; rarity affects only speed.

#define HIDDEN 16
#define NPOS (128 * 4096)

__device__ float4 g_A[16];
__device__ float4 g_C[16];
__device__ float  g_xguard;
__device__ int    g_fix_count;
__device__ int    g_fix_list[NPOS];   // worst case: every position

__global__ void prep_kernel(const float* __restrict__ w1,
                            const float* __restrict__ b1,
                            const float* __restrict__ w2,
                            const float* __restrict__ b2) {
    int q = threadIdx.x;            // 0..15, owns dims 4q..4q+3
    if (q >= 16) return;
    if (q == 0) g_fix_count = 0;    // reset every launch (graph-replay safe)
    int d0 = q * 4;

    float A[4] = {0.f, 0.f, 0.f, 0.f};
    float C[4] = {b2[d0], b2[d0+1], b2[d0+2], b2[d0+3]};
    float xlo = -3.4e38f;
    #pragma unroll
    for (int j = 0; j < HIDDEN; j++) {
        float w1j = w1[j], b1j = b1[j];
        if (w1j != 0.f) xlo = fmaxf(xlo, -b1j / w1j);
        #pragma unroll
        for (int c = 0; c < 4; c++) {
            float w2v = w2[(d0 + c) * HIDDEN + j];
            if (w1j > 0.f) {            // active for large x
                A[c] = fmaf(w2v, w1j, A[c]);
                C[c] = fmaf(w2v, b1j, C[c]);
            } else if (w1j == 0.f) {    // constant unit
                C[c] = fmaf(w2v, fmaxf(b1j, 0.f), C[c]);
            }
        }
    }
    g_A[q] = make_float4(A[0], A[1], A[2], A[3]);
    g_C[q] = make_float4(C[0], C[1], C[2], C[3]);
    if (q == 0) g_xguard = xlo + 0.5f;   // margin swallows divide rounding
}

__global__ void __launch_bounds__(256) embedder_kernel(
    const float* __restrict__ input_ids,
    const int* __restrict__ type_mask,
    const float4* __restrict__ emb_table,   // [VOCAB][16] float4
    float4* __restrict__ out,
    int n_vec)
{
    int v = blockIdx.x * blockDim.x + threadIdx.x;
    if (v >= n_vec) return;
    int q   = v & 15;
    int pos = v >> 4;

    float x = __ldg(&input_ids[pos]);
    int   m = __ldg(&type_mask[pos]);

    float4 r;
    if (m) {
        // L2-only gather; table stays L2-resident (stores are evict-first)
        r = __ldcg(&emb_table[((int)x) * 16 + q]);
    } else {
        float4 A = g_A[q];
        float4 C = g_C[q];
        r = make_float4(fmaf(A.x, x, C.x), fmaf(A.y, x, C.y),
                        fmaf(A.z, x, C.z), fmaf(A.w, x, C.w));
        if (x < g_xguard && q == 0) {        // rare: record for exact fixup
            int slot = atomicAdd(&g_fix_count, 1);
            g_fix_list[slot] = pos;
        }
    }
    __stcs(&out[v], r);                      // streaming store, evict-first
}

__global__ void __launch_bounds__(256) fixup_kernel(
    const float* __restrict__ input_ids,
    const float* __restrict__ w1,
    const float* __restrict__ b1,
    const float* __restrict__ w2,
    const float* __restrict__ b2,
    float4* __restrict__ out)
{
    int n = g_fix_count;
    for (int i = blockIdx.x * blockDim.x + threadIdx.x; i < n;
         i += gridDim.x * blockDim.x) {
        int pos = g_fix_list[i];
        float x = input_ids[pos];

        float h[HIDDEN];
        #pragma unroll
        for (int j = 0; j < HIDDEN; j++)
            h[j] = fmaxf(fmaf(w1[j], x, b1[j]), 0.f);

        #pragma unroll
        for (int qq = 0; qq < 16; qq++) {
            float a[4];
            #pragma unroll
            for (int c = 0; c < 4; c++) {
                int d = qq * 4 + c;
                float s = b2[d];
                #pragma unroll
                for (int j = 0; j < HIDDEN; j++)
                    s = fmaf(w2[d * HIDDEN + j], h[j], s);
                a[c] = s;
            }
            out[pos * 16 + qq] = make_float4(a[0], a[1], a[2], a[3]);
        }
    }
}

extern "C" void kernel_launch(void* const* d_in, const int* in_sizes, int n_in,
                              void* d_out, int out_size) {
    const float*  input_ids = (const float*)d_in[0];
    const int*    type_mask = (const int*)d_in[1];
    const float4* emb_table = (const float4*)d_in[2];
    const float*  w1        = (const float*)d_in[3];
    const float*  b1        = (const float*)d_in[4];
    const float*  w2        = (const float*)d_in[5];
    const float*  b2        = (const float*)d_in[6];
    float4* out = (float4*)d_out;

    int n_vec = out_size / 4;               // 8.4M float4s

    prep_kernel<<<1, 16>>>(w1, b1, w2, b2);

    int threads = 256;
    int blocks = (n_vec + threads - 1) / threads;   // full grid, one-shot
    embedder_kernel<<<blocks, threads>>>(input_ids, type_mask, emb_table,
                                         out, n_vec);

    fixup_kernel<<<32, 256>>>(input_ids, w1, b1, w2, b2, out);
}